// round 1
// baseline (speedup 1.0000x reference)
#include <cuda_runtime.h>
#include <cuda_bf16.h>

// Problem constants (from reference: S=8192, G=1024, T=4096, E=16384)
#define E_N 16384
#define T_N 4096
#define S_N 8192
#define G_N 1024
#define CHUNK 32
#define NCHUNKS (T_N / CHUNK)  // 128

// Per-event precomputed record: {ts, te, group, w(bits)}
__device__ int4 g_events[E_N];

// ---------------------------------------------------------------------------
// Kernel 1: per-event preprocessing.
// ts = lower_bound(t0, start)  (first i with t0[i] >= start)
// te = lower_bound(t0, end)    (first i with t0[i] >= end)
// Active range is [ts, te):  start <= t0[i] < end  (t0 sorted ascending).
// ---------------------------------------------------------------------------
__global__ void preprocess_kernel(const int*   __restrict__ index,
                                  const float* __restrict__ rate,
                                  const float* __restrict__ start,
                                  const float* __restrict__ endt,
                                  const float* __restrict__ t0,
                                  const int*   __restrict__ group_id,
                                  const float* __restrict__ weights) {
    __shared__ float s_t0[T_N];  // 16 KB
    for (int i = threadIdx.x; i < T_N; i += blockDim.x) s_t0[i] = t0[i];
    __syncthreads();

    int e = blockIdx.x * blockDim.x + threadIdx.x;
    if (e >= E_N) return;

    float st = start[e];
    float en = endt[e];

    // lower_bound over shared t0 (12 steps)
    int lo = 0, hi = T_N;
    #pragma unroll 1
    while (lo < hi) { int mid = (lo + hi) >> 1; if (s_t0[mid] < st) lo = mid + 1; else hi = mid; }
    int ts = lo;

    lo = 0; hi = T_N;
    #pragma unroll 1
    while (lo < hi) { int mid = (lo + hi) >> 1; if (s_t0[mid] < en) lo = mid + 1; else hi = mid; }
    int te = lo;

    int src = index[e];
    float w = rate[e] * weights[src];
    int g = group_id[src];

    g_events[e] = make_int4(ts, te, g, __float_as_int(w));
}

// ---------------------------------------------------------------------------
// Kernel 2: fused difference-array build + prefix scan + output write.
// One block per 32-timestep chunk. Shared diff tile [CHUNK][G] = 128 KB.
// Clamping ts to the chunk start folds the "carry" of already-active events
// into row 0 of the tile, so no cross-chunk scan pass is needed.
// ---------------------------------------------------------------------------
__global__ void __launch_bounds__(G_N, 1)
scan_kernel(float* __restrict__ out) {
    extern __shared__ float diff[];  // CHUNK * G_N floats
    const int tbeg = blockIdx.x * CHUNK;
    const int tid  = threadIdx.x;

    // Zero the tile
    #pragma unroll
    for (int i = 0; i < CHUNK; i++)
        diff[i * G_N + tid] = 0.0f;
    __syncthreads();

    // Sweep all events, range-clamped to this chunk
    #pragma unroll 4
    for (int e = tid; e < E_N; e += G_N) {
        int4 ev = g_events[e];
        int lts = ev.x - tbeg;
        int lte = ev.y - tbeg;
        lts = lts < 0 ? 0 : lts;
        lte = lte > CHUNK ? CHUNK : lte;
        if (lte > lts) {
            float w = __int_as_float(ev.w);
            atomicAdd(&diff[lts * G_N + ev.z], w);
            if (lte < CHUNK)
                atomicAdd(&diff[lte * G_N + ev.z], -w);
        }
    }
    __syncthreads();

    // Per-group serial prefix over the chunk; thread tid owns column g=tid.
    // LDS row reads are conflict-free (consecutive g -> consecutive banks),
    // STG rows are fully coalesced (32 consecutive floats per warp).
    float acc = 0.0f;
    #pragma unroll
    for (int t = 0; t < CHUNK; t++) {
        acc += diff[t * G_N + tid];
        out[(size_t)(tbeg + t) * G_N + tid] = acc;
    }
}

// ---------------------------------------------------------------------------
extern "C" void kernel_launch(void* const* d_in, const int* in_sizes, int n_in,
                              void* d_out, int out_size) {
    const int*   index    = (const int*)  d_in[0];
    const float* rate     = (const float*)d_in[1];
    const float* start    = (const float*)d_in[2];
    const float* endt     = (const float*)d_in[3];
    const float* t0       = (const float*)d_in[4];
    const int*   group_id = (const int*)  d_in[5];
    const float* weights  = (const float*)d_in[6];
    float* out = (float*)d_out;

    // 128 KB dynamic smem opt-in (idempotent, capture-safe: not a stream op)
    cudaFuncSetAttribute(scan_kernel,
                         cudaFuncAttributeMaxDynamicSharedMemorySize,
                         CHUNK * G_N * (int)sizeof(float));

    preprocess_kernel<<<E_N / 256, 256>>>(index, rate, start, endt, t0,
                                          group_id, weights);
    scan_kernel<<<NCHUNKS, G_N, CHUNK * G_N * (int)sizeof(float)>>>(out);
}